// round 13
// baseline (speedup 1.0000x reference)
#include <cuda_runtime.h>
#include <cstdint>
#include <cstddef>

#define NPIX 2304          // 48*48
#define HPW  48
#define BSZ  4
#define CDIM 256
#define NH   8
#define HD   32
// ATT_SCALE * log2(e): softmax runs in log2 domain, exp -> ex2
#define QSCALE 0.2550539239271926f

// ---------------- scratch ----------------
__device__ float g_v4[(size_t)BSZ * CDIM * NPIX];
__device__ float g_pe[(size_t)BSZ * CDIM * NPIX];
__device__ float g_o [(size_t)BSZ * CDIM * NPIX];
// packed bf16 staging for attention (fragment-permuted layouts)
__device__ __align__(16) uint32_t g_qbf[(size_t)BSZ * NH * NPIX * 16];   // [bh][j][perm d2]
__device__ __align__(16) uint32_t g_kbf[(size_t)BSZ * NH * NPIX * 16];   // [bh][j][perm d2]
__device__ __align__(16) uint32_t g_vbf[(size_t)BSZ * CDIM * (NPIX/2)]; // [row][block][perm j2]

// ---------------- helpers ----------------
__device__ __forceinline__ uint32_t pkbf(float lo, float hi) {
    uint32_t r; asm("cvt.rn.bf16x2.f32 %0, %1, %2;" : "=r"(r) : "f"(hi), "f"(lo)); return r;
}
__device__ __forceinline__ uint32_t f2tf32(float f) {
    uint32_t r; asm("cvt.rna.tf32.f32 %0, %1;" : "=r"(r) : "f"(f)); return r;
}
__device__ __forceinline__ float ex2f(float x) {
    float r; asm("ex2.approx.ftz.f32 %0, %1;" : "=f"(r) : "f"(x)); return r;
}
__device__ __forceinline__ uint32_t smem_u32(const void* p) {
    uint32_t a;
    asm("{ .reg .u64 t; cvta.to.shared.u64 t, %1; cvt.u32.u64 %0, t; }" : "=r"(a) : "l"(p));
    return a;
}
// m16n8k16 bf16 mma, C/D fp32
__device__ __forceinline__ void mma16(float c[4], const uint32_t a[4], uint32_t b0, uint32_t b1) {
    asm volatile(
        "mma.sync.aligned.m16n8k16.row.col.f32.bf16.bf16.f32 "
        "{%0,%1,%2,%3}, {%4,%5,%6,%7}, {%8,%9}, {%0,%1,%2,%3};"
        : "+f"(c[0]), "+f"(c[1]), "+f"(c[2]), "+f"(c[3])
        : "r"(a[0]), "r"(a[1]), "r"(a[2]), "r"(a[3]), "r"(b0), "r"(b1));
}
// m16n8k8 tf32 mma, C/D fp32
__device__ __forceinline__ void mma8(float c[4], const uint32_t a[4], uint32_t b0, uint32_t b1) {
    asm volatile(
        "mma.sync.aligned.m16n8k8.row.col.f32.tf32.tf32.f32 "
        "{%0,%1,%2,%3}, {%4,%5,%6,%7}, {%8,%9}, {%0,%1,%2,%3};"
        : "+f"(c[0]), "+f"(c[1]), "+f"(c[2]), "+f"(c[3])
        : "r"(a[0]), "r"(a[1]), "r"(a[2]), "r"(a[3]), "r"(b0), "r"(b1));
}

#define WT_STR 36
#define AT_STR 136

// ---------------- qk conv: transposed-output GEMM -> packed bf16 q/k directly ----------------
// grid (NPIX/128, 512/128, BSZ), block 256 = 8 warps (4m x 2n)
__global__ __launch_bounds__(256) void convqk_tc_kernel(
    const float* __restrict__ X, const float* __restrict__ W,
    const float* __restrict__ bias,
    uint32_t* __restrict__ qbf, uint32_t* __restrict__ kbf)
{
    __shared__ uint32_t Wt[128 * WT_STR];   // [d][c] tf32
    __shared__ uint32_t At[32 * AT_STR];    // [c][j] tf32

    const int t    = threadIdx.x;
    const int w    = t >> 5;
    const int lane = t & 31;
    const int gid  = lane >> 2;
    const int tg   = lane & 3;
    const int wm   = w >> 1;     // j-warps
    const int wn   = w & 1;      // d-warps

    const int b  = blockIdx.z;
    const int o0 = blockIdx.y * 128;   // channel base (2 heads)
    const int n0 = blockIdx.x * 128;   // pixel base

    const float* Xb = X + (size_t)b * CDIM * NPIX;

    float acc[2][8][4];
    #pragma unroll
    for (int mi = 0; mi < 2; mi++)
        #pragma unroll
        for (int nc = 0; nc < 8; nc++)
            #pragma unroll
            for (int r = 0; r < 4; r++) acc[mi][nc][r] = 0.f;

    for (int c0 = 0; c0 < CDIM; c0 += 32) {
        __syncthreads();
        #pragma unroll
        for (int r = 0; r < 16; r++) {
            int e = t + r * 256;
            int oo = e >> 5, cc = e & 31;
            Wt[oo * WT_STR + cc] = f2tf32(W[(size_t)(o0 + oo) * CDIM + c0 + cc]);
        }
        #pragma unroll
        for (int r = 0; r < 16; r++) {
            int e = t + r * 256;
            int cc = e >> 7, nn = e & 127;
            At[cc * AT_STR + nn] = f2tf32(Xb[(size_t)(c0 + cc) * NPIX + n0 + nn]);
        }
        __syncthreads();

        #pragma unroll
        for (int k8 = 0; k8 < 4; k8++) {
            const int kt = k8 * 8 + tg;
            uint32_t a0[4], a1[4];
            {
                const int jb = wm * 32;
                a0[0] = At[kt * AT_STR + jb + gid];
                a0[1] = At[kt * AT_STR + jb + gid + 8];
                a0[2] = At[(kt + 4) * AT_STR + jb + gid];
                a0[3] = At[(kt + 4) * AT_STR + jb + gid + 8];
                a1[0] = At[kt * AT_STR + jb + 16 + gid];
                a1[1] = At[kt * AT_STR + jb + 16 + gid + 8];
                a1[2] = At[(kt + 4) * AT_STR + jb + 16 + gid];
                a1[3] = At[(kt + 4) * AT_STR + jb + 16 + gid + 8];
            }
            #pragma unroll
            for (int nc = 0; nc < 8; nc++) {
                const int d = wn * 64 + nc * 8 + gid;
                uint32_t b0 = Wt[d * WT_STR + kt];
                uint32_t b1 = Wt[d * WT_STR + kt + 4];
                mma8(acc[0][nc], a0, b0, b1);
                mma8(acc[1][nc], a1, b0, b1);
            }
        }
    }

    const int head = (o0 >> 6) + wn;
    const int jb = n0 + wm * 32;
    #pragma unroll
    for (int mi = 0; mi < 2; mi++) {
        const int j_lo = jb + mi * 16 + gid;
        const int j_hi = j_lo + 8;
        #pragma unroll
        for (int half = 0; half < 2; half++) {
            uint32_t wlo[4], whi[4];
            #pragma unroll
            for (int s = 0; s < 4; s++) {
                int nc = half * 4 + s;
                int ch = o0 + wn * 64 + nc * 8 + 2 * tg;
                float b0v = bias[ch], b1v = bias[ch + 1];
                float v0 = acc[mi][nc][0] + b0v;
                float v1 = acc[mi][nc][1] + b1v;
                float v2 = acc[mi][nc][2] + b0v;
                float v3 = acc[mi][nc][3] + b1v;
                if (half == 0) { v0 *= QSCALE; v1 *= QSCALE; v2 *= QSCALE; v3 *= QSCALE; }
                wlo[s] = pkbf(v0, v1);
                whi[s] = pkbf(v2, v3);
            }
            uint32_t* dst = (half ? kbf : qbf) + (size_t)(b * NH + head) * NPIX * 16;
            *reinterpret_cast<uint4*>(&dst[(size_t)j_lo * 16 + 4 * tg]) =
                make_uint4(wlo[0], wlo[1], wlo[2], wlo[3]);
            *reinterpret_cast<uint4*>(&dst[(size_t)j_hi * 16 + 4 * tg]) =
                make_uint4(whi[0], whi[1], whi[2], whi[3]);
        }
    }
}

// ---------------- tf32 tensor-core 1x1 conv; optional packed-bf16 dual output ----------------
__global__ __launch_bounds__(256) void conv_tc_kernel(
    const float* __restrict__ A, const float* __restrict__ A2,
    const float* __restrict__ W, const float* __restrict__ bias,
    float* __restrict__ Y, uint32_t* __restrict__ vpack, int O)
{
    __shared__ uint32_t Wt[128 * WT_STR];
    __shared__ uint32_t At[32 * AT_STR];

    const int t    = threadIdx.x;
    const int w    = t >> 5;
    const int lane = t & 31;
    const int gid  = lane >> 2;
    const int tg   = lane & 3;
    const int wm   = w >> 1;
    const int wn   = w & 1;

    const int b  = blockIdx.z;
    const int o0 = blockIdx.y * 128;
    const int n0 = blockIdx.x * 128;

    const float* Ab  = A  + (size_t)b * CDIM * NPIX;
    const float* A2b = A2 ? A2 + (size_t)b * CDIM * NPIX : nullptr;

    float acc[2][8][4];
    #pragma unroll
    for (int mi = 0; mi < 2; mi++)
        #pragma unroll
        for (int nc = 0; nc < 8; nc++)
            #pragma unroll
            for (int r = 0; r < 4; r++) acc[mi][nc][r] = 0.f;

    for (int c0 = 0; c0 < CDIM; c0 += 32) {
        __syncthreads();
        #pragma unroll
        for (int r = 0; r < 16; r++) {
            int e = t + r * 256;
            int oo = e >> 5, cc = e & 31;
            Wt[oo * WT_STR + cc] = f2tf32(W[(size_t)(o0 + oo) * CDIM + c0 + cc]);
        }
        #pragma unroll
        for (int r = 0; r < 16; r++) {
            int e = t + r * 256;
            int cc = e >> 7, nn = e & 127;
            float v = Ab[(size_t)(c0 + cc) * NPIX + n0 + nn];
            if (A2b) v += A2b[(size_t)(c0 + cc) * NPIX + n0 + nn];
            At[cc * AT_STR + nn] = f2tf32(v);
        }
        __syncthreads();

        #pragma unroll
        for (int k8 = 0; k8 < 4; k8++) {
            const int kt = k8 * 8 + tg;
            uint32_t a0[4], a1[4];
            {
                const int ob = wm * 32;
                a0[0] = Wt[(ob + gid) * WT_STR + kt];
                a0[1] = Wt[(ob + gid + 8) * WT_STR + kt];
                a0[2] = Wt[(ob + gid) * WT_STR + kt + 4];
                a0[3] = Wt[(ob + gid + 8) * WT_STR + kt + 4];
                a1[0] = Wt[(ob + 16 + gid) * WT_STR + kt];
                a1[1] = Wt[(ob + 16 + gid + 8) * WT_STR + kt];
                a1[2] = Wt[(ob + 16 + gid) * WT_STR + kt + 4];
                a1[3] = Wt[(ob + 16 + gid + 8) * WT_STR + kt + 4];
            }
            #pragma unroll
            for (int nc = 0; nc < 8; nc++) {
                const int n = wn * 64 + nc * 8 + gid;
                uint32_t b0 = At[kt * AT_STR + n];
                uint32_t b1 = At[(kt + 4) * AT_STR + n];
                mma8(acc[0][nc], a0, b0, b1);
                mma8(acc[1][nc], a1, b0, b1);
            }
        }
    }

    #pragma unroll
    for (int mi = 0; mi < 2; mi++) {
        const int o_lo = o0 + wm * 32 + mi * 16 + gid;
        const int o_hi = o_lo + 8;
        const float b_lo = bias[o_lo], b_hi = bias[o_hi];
        #pragma unroll
        for (int nc = 0; nc < 8; nc++) {
            const int n = n0 + wn * 64 + nc * 8 + 2 * tg;
            float2 lo = { acc[mi][nc][0] + b_lo, acc[mi][nc][1] + b_lo };
            float2 hi = { acc[mi][nc][2] + b_hi, acc[mi][nc][3] + b_hi };
            *reinterpret_cast<float2*>(&Y[((size_t)b * O + o_lo) * NPIX + n]) = lo;
            *reinterpret_cast<float2*>(&Y[((size_t)b * O + o_hi) * NPIX + n]) = hi;
        }
        if (vpack) {
            uint32_t wlo[8], whi[8];
            #pragma unroll
            for (int nc = 0; nc < 8; nc++) {
                wlo[nc] = pkbf(acc[mi][nc][0] + b_lo, acc[mi][nc][1] + b_lo);
                whi[nc] = pkbf(acc[mi][nc][2] + b_hi, acc[mi][nc][3] + b_hi);
            }
            const int j2base = (n0 >> 1) + wn * 32;
            uint32_t* dlo = vpack + ((size_t)b * CDIM + o_lo) * (NPIX / 2) + j2base + 8 * tg;
            uint32_t* dhi = vpack + ((size_t)b * CDIM + o_hi) * (NPIX / 2) + j2base + 8 * tg;
            *reinterpret_cast<uint4*>(dlo)     = make_uint4(wlo[0], wlo[1], wlo[2], wlo[3]);
            *reinterpret_cast<uint4*>(dlo + 4) = make_uint4(wlo[4], wlo[5], wlo[6], wlo[7]);
            *reinterpret_cast<uint4*>(dhi)     = make_uint4(whi[0], whi[1], whi[2], whi[3]);
            *reinterpret_cast<uint4*>(dhi + 4) = make_uint4(whi[4], whi[5], whi[6], whi[7]);
        }
    }
}

#define KSTR 16
#define VSTR 36
#define NTILE (NPIX / 64)   // 36
#define K_BYTES (64 * KSTR * 4)   // 4096
#define V_BYTES (32 * VSTR * 4)   // 4608

// ---------------- bf16 flash attention (unchanged from R12) ----------------
__global__ __launch_bounds__(256, 4) void attn_bf16_kernel(
    const uint32_t* __restrict__ qbf, const uint32_t* __restrict__ kbf,
    const uint32_t* __restrict__ vbf, float* __restrict__ o)
{
    __shared__ __align__(16) uint32_t K2[2][64 * KSTR];
    __shared__ __align__(16) uint32_t V2[2][32 * VSTR];

    const int t    = threadIdx.x;
    const int w    = t >> 5;
    const int lane = t & 31;
    const int gid  = lane >> 2;
    const int tg   = lane & 3;

    const int bh = blockIdx.y;
    const int b  = bh >> 3, h = bh & 7;
    const int iw = blockIdx.x * 128 + w * 16;

    const uint32_t* qb = qbf + (size_t)bh * NPIX * 16;
    const uint32_t* kb = kbf + (size_t)bh * NPIX * 16;
    const uint32_t* vb = vbf + ((size_t)b * CDIM + h * HD) * (NPIX / 2);

    const uint32_t k2base = smem_u32(&K2[0][0]);
    const uint32_t v2base = smem_u32(&V2[0][0]);

    uint32_t qa[2][4];
    {
        const int ilo = iw + gid, ihi = iw + gid + 8;
        uint4 qlo = *reinterpret_cast<const uint4*>(&qb[(size_t)ilo * 16 + 4 * tg]);
        uint4 qhi = *reinterpret_cast<const uint4*>(&qb[(size_t)ihi * 16 + 4 * tg]);
        qa[0][0] = qlo.x; qa[0][2] = qlo.y; qa[1][0] = qlo.z; qa[1][2] = qlo.w;
        qa[0][1] = qhi.x; qa[0][3] = qhi.y; qa[1][1] = qhi.z; qa[1][3] = qhi.w;
    }

    float l0 = 0.f, l1 = 0.f;
    float oacc[4][4];
    #pragma unroll
    for (int i = 0; i < 4; i++)
        #pragma unroll
        for (int j = 0; j < 4; j++) oacc[i][j] = 0.f;

    const int kj = t >> 2, kc_ = t & 3;
    const int vd = t >> 3, vc_ = t & 7;
    auto load_tile = [&](int j0, int buf) {
        uint32_t kdst = k2base + buf * K_BYTES + kj * 64 + kc_ * 16;
        const uint32_t* ksrc = kb + (size_t)(j0 + kj) * 16 + kc_ * 4;
        asm volatile("cp.async.cg.shared.global [%0], [%1], 16;" :: "r"(kdst), "l"(ksrc));
        uint32_t vdst = v2base + buf * V_BYTES + vd * 144 + vc_ * 16;
        const uint32_t* vsrc = vb + (size_t)vd * (NPIX / 2) + (j0 >> 1) + vc_ * 4;
        asm volatile("cp.async.cg.shared.global [%0], [%1], 16;" :: "r"(vdst), "l"(vsrc));
        asm volatile("cp.async.commit_group;");
    };

    load_tile(0, 0);
    asm volatile("cp.async.wait_group 0;" ::: "memory");
    __syncthreads();

    for (int jt = 0; jt < NTILE; jt++) {
        const int cur = jt & 1;
        if (jt + 1 < NTILE) load_tile((jt + 1) * 64, cur ^ 1);

        uint32_t pa[4][4];
        #pragma unroll
        for (int kc = 0; kc < 4; kc++) {
            float s0[4], s1[4];
            {
                uint4 kw = *reinterpret_cast<const uint4*>(
                    &K2[cur][(16 * kc + gid) * KSTR + 4 * tg]);
                s0[0] = s0[1] = s0[2] = s0[3] = 0.f;
                mma16(s0, qa[0], kw.x, kw.y);
                mma16(s0, qa[1], kw.z, kw.w);
            }
            {
                uint4 kw = *reinterpret_cast<const uint4*>(
                    &K2[cur][(16 * kc + 8 + gid) * KSTR + 4 * tg]);
                s1[0] = s1[1] = s1[2] = s1[3] = 0.f;
                mma16(s1, qa[0], kw.x, kw.y);
                mma16(s1, qa[1], kw.z, kw.w);
            }
            s0[0] = ex2f(s0[0]); s0[1] = ex2f(s0[1]);
            s0[2] = ex2f(s0[2]); s0[3] = ex2f(s0[3]);
            s1[0] = ex2f(s1[0]); s1[1] = ex2f(s1[1]);
            s1[2] = ex2f(s1[2]); s1[3] = ex2f(s1[3]);
            l0 += s0[0] + s0[1] + s1[0] + s1[1];
            l1 += s0[2] + s0[3] + s1[2] + s1[3];
            pa[kc][0] = pkbf(s0[0], s0[1]);
            pa[kc][1] = pkbf(s0[2], s0[3]);
            pa[kc][2] = pkbf(s1[0], s1[1]);
            pa[kc][3] = pkbf(s1[2], s1[3]);
        }

        #pragma unroll
        for (int nc2 = 0; nc2 < 4; nc2++) {
            const int drow = (8 * nc2 + gid) * VSTR;
            uint4 v1 = *reinterpret_cast<const uint4*>(&V2[cur][drow + 8 * tg]);
            uint4 v2 = *reinterpret_cast<const uint4*>(&V2[cur][drow + 8 * tg + 4]);
            mma16(oacc[nc2], pa[0], v1.x, v1.y);
            mma16(oacc[nc2], pa[1], v1.z, v1.w);
            mma16(oacc[nc2], pa[2], v2.x, v2.y);
            mma16(oacc[nc2], pa[3], v2.z, v2.w);
        }

        asm volatile("cp.async.wait_group 0;" ::: "memory");
        __syncthreads();
    }

    l0 += __shfl_xor_sync(0xffffffffu, l0, 1);
    l0 += __shfl_xor_sync(0xffffffffu, l0, 2);
    l1 += __shfl_xor_sync(0xffffffffu, l1, 1);
    l1 += __shfl_xor_sync(0xffffffffu, l1, 2);

    const float inv0 = 1.f / l0, inv1 = 1.f / l1;
    float* ob = o + ((size_t)b * CDIM + h * HD) * NPIX;
    const int i_lo = iw + gid, i_hi = iw + gid + 8;
    #pragma unroll
    for (int nc2 = 0; nc2 < 4; nc2++) {
        int d = 8 * nc2 + 2 * tg;
        ob[(size_t)d * NPIX + i_lo]       = oacc[nc2][0] * inv0;
        ob[(size_t)(d + 1) * NPIX + i_lo] = oacc[nc2][1] * inv0;
        ob[(size_t)d * NPIX + i_hi]       = oacc[nc2][2] * inv1;
        ob[(size_t)(d + 1) * NPIX + i_hi] = oacc[nc2][3] * inv1;
    }
}

// ---------------- depthwise 3x3 ----------------
__global__ __launch_bounds__(256) void dwconv_kernel(
    const float* __restrict__ v4, const float* __restrict__ w_pe,
    const float* __restrict__ b_pe, float* __restrict__ pe)
{
    __shared__ float plane[NPIX];
    const int bc = blockIdx.x;
    const int c  = bc & (CDIM - 1);
    const int t  = threadIdx.x;

    const float* src = v4 + (size_t)bc * NPIX;
    #pragma unroll
    for (int r = 0; r < 9; r++) plane[t + r * 256] = src[t + r * 256];

    float w[9];
    #pragma unroll
    for (int k = 0; k < 9; k++) w[k] = w_pe[c * 9 + k];
    const float bias = b_pe[c];
    __syncthreads();

    float* dst = pe + (size_t)bc * NPIX;
    #pragma unroll
    for (int r = 0; r < 9; r++) {
        int idx = t + r * 256;
        int y = idx / HPW, x = idx - y * HPW;
        float s = bias;
        #pragma unroll
        for (int dy = 0; dy < 3; dy++) {
            int yy = y + dy - 1;
            if (yy < 0 || yy >= HPW) continue;
            #pragma unroll
            for (int dx = 0; dx < 3; dx++) {
                int xx = x + dx - 1;
                if (xx < 0 || xx >= HPW) continue;
                s += plane[yy * HPW + xx] * w[dy * 3 + dx];
            }
        }
        dst[idx] = s;
    }
}

// ---------------- launch: fork/join stream DAG (graph-capture legal) ----------------
extern "C" void kernel_launch(void* const* d_in, const int* in_sizes, int n_in,
                              void* d_out, int out_size)
{
    const float* x      = (const float*)d_in[0];
    const float* w_qk   = (const float*)d_in[1];
    const float* b_qk   = (const float*)d_in[2];
    const float* w_v    = (const float*)d_in[3];
    const float* b_v    = (const float*)d_in[4];
    const float* w_pe   = (const float*)d_in[5];
    const float* b_pe   = (const float*)d_in[6];
    const float* w_proj = (const float*)d_in[7];
    const float* b_proj = (const float*)d_in[8];
    float* out = (float*)d_out;

    float *v4p, *pep, *op;
    uint32_t *qbfp, *kbfp, *vbfp;
    cudaGetSymbolAddress((void**)&v4p, g_v4);
    cudaGetSymbolAddress((void**)&pep, g_pe);
    cudaGetSymbolAddress((void**)&op,  g_o);
    cudaGetSymbolAddress((void**)&qbfp, g_qbf);
    cudaGetSymbolAddress((void**)&kbfp, g_kbf);
    cudaGetSymbolAddress((void**)&vbfp, g_vbf);

    static cudaStream_t s1 = nullptr, s2 = nullptr;
    static cudaEvent_t e_fork = nullptr, e_qk = nullptr, e_v = nullptr, e_dw = nullptr;
    if (!s1) {
        cudaStreamCreateWithFlags(&s1, cudaStreamNonBlocking);
        cudaStreamCreateWithFlags(&s2, cudaStreamNonBlocking);
        cudaEventCreateWithFlags(&e_fork, cudaEventDisableTiming);
        cudaEventCreateWithFlags(&e_qk, cudaEventDisableTiming);
        cudaEventCreateWithFlags(&e_v, cudaEventDisableTiming);
        cudaEventCreateWithFlags(&e_dw, cudaEventDisableTiming);
    }

    // fork from the main (capture-origin) stream
    cudaEventRecord(e_fork, 0);
    cudaStreamWaitEvent(s1, e_fork, 0);
    cudaStreamWaitEvent(s2, e_fork, 0);

    // s1: qk conv -> packed bf16 q/k
    convqk_tc_kernel<<<dim3(NPIX/128, 512/128, BSZ), 256, 0, s1>>>(x, w_qk, b_qk, qbfp, kbfp);
    cudaEventRecord(e_qk, s1);

    // s2: v conv (fp32 + packed bf16), then dwconv (overlaps attention on main)
    conv_tc_kernel<<<dim3(NPIX/128, CDIM/128, BSZ), 256, 0, s2>>>(x, nullptr, w_v, b_v, v4p, vbfp, CDIM);
    cudaEventRecord(e_v, s2);
    dwconv_kernel<<<BSZ * CDIM, 256, 0, s2>>>(v4p, w_pe, b_pe, pep);
    cudaEventRecord(e_dw, s2);

    // main: attention after qk + v; proj after attention + dwconv
    cudaStreamWaitEvent(0, e_qk, 0);
    cudaStreamWaitEvent(0, e_v, 0);
    attn_bf16_kernel<<<dim3(NPIX/128, BSZ * NH), 256>>>(qbfp, kbfp, vbfp, op);
    cudaStreamWaitEvent(0, e_dw, 0);
    conv_tc_kernel<<<dim3(NPIX/128, CDIM/128, BSZ), 256>>>(op, pep, w_proj, b_proj, out, nullptr, CDIM);
}

// round 14
// speedup vs baseline: 1.0682x; 1.0682x over previous
#include <cuda_runtime.h>
#include <cstdint>
#include <cstddef>

#define NPIX 2304          // 48*48
#define HPW  48
#define BSZ  4
#define CDIM 256
#define NH   8
#define HD   32
// ATT_SCALE * log2(e): softmax runs in log2 domain, exp -> ex2
#define QSCALE 0.2550539239271926f

// ---------------- scratch ----------------
__device__ float g_v4[(size_t)BSZ * CDIM * NPIX];
__device__ float g_pe[(size_t)BSZ * CDIM * NPIX];
__device__ float g_o [(size_t)BSZ * CDIM * NPIX];
// packed bf16 staging for attention (fragment-permuted layouts)
__device__ __align__(16) uint32_t g_qbf[(size_t)BSZ * NH * NPIX * 16];   // [bh][j][perm d2]
__device__ __align__(16) uint32_t g_kbf[(size_t)BSZ * NH * NPIX * 16];   // [bh][j][perm d2]
__device__ __align__(16) uint32_t g_vbf[(size_t)BSZ * CDIM * (NPIX/2)]; // [row][block][perm j2]

// ---------------- helpers ----------------
__device__ __forceinline__ uint32_t pkbf(float lo, float hi) {
    uint32_t r; asm("cvt.rn.bf16x2.f32 %0, %1, %2;" : "=r"(r) : "f"(hi), "f"(lo)); return r;
}
__device__ __forceinline__ uint32_t f2tf32(float f) {
    uint32_t r; asm("cvt.rna.tf32.f32 %0, %1;" : "=r"(r) : "f"(f)); return r;
}
__device__ __forceinline__ float ex2f(float x) {
    float r; asm("ex2.approx.ftz.f32 %0, %1;" : "=f"(r) : "f"(x)); return r;
}
__device__ __forceinline__ uint32_t smem_u32(const void* p) {
    uint32_t a;
    asm("{ .reg .u64 t; cvta.to.shared.u64 t, %1; cvt.u32.u64 %0, t; }" : "=r"(a) : "l"(p));
    return a;
}
// m16n8k16 bf16 mma, C/D fp32
__device__ __forceinline__ void mma16(float c[4], const uint32_t a[4], uint32_t b0, uint32_t b1) {
    asm volatile(
        "mma.sync.aligned.m16n8k16.row.col.f32.bf16.bf16.f32 "
        "{%0,%1,%2,%3}, {%4,%5,%6,%7}, {%8,%9}, {%0,%1,%2,%3};"
        : "+f"(c[0]), "+f"(c[1]), "+f"(c[2]), "+f"(c[3])
        : "r"(a[0]), "r"(a[1]), "r"(a[2]), "r"(a[3]), "r"(b0), "r"(b1));
}
// m16n8k8 tf32 mma, C/D fp32
__device__ __forceinline__ void mma8(float c[4], const uint32_t a[4], uint32_t b0, uint32_t b1) {
    asm volatile(
        "mma.sync.aligned.m16n8k8.row.col.f32.tf32.tf32.f32 "
        "{%0,%1,%2,%3}, {%4,%5,%6,%7}, {%8,%9}, {%0,%1,%2,%3};"
        : "+f"(c[0]), "+f"(c[1]), "+f"(c[2]), "+f"(c[3])
        : "r"(a[0]), "r"(a[1]), "r"(a[2]), "r"(a[3]), "r"(b0), "r"(b1));
}

#define WT_STR 36
#define AT_STR 136

// ---------------- fused producer GEMM: qk path (y<4) + v path (y>=4) ----------------
// grid (NPIX/128, 6, BSZ), block 256 = 8 warps (4m x 2n)
__global__ __launch_bounds__(256) void producer_tc_kernel(
    const float* __restrict__ X,
    const float* __restrict__ Wqk, const float* __restrict__ Bqk,
    const float* __restrict__ Wv,  const float* __restrict__ Bv,
    uint32_t* __restrict__ qbf, uint32_t* __restrict__ kbf,
    float* __restrict__ v4, uint32_t* __restrict__ vbf)
{
    __shared__ uint32_t Wt[128 * WT_STR];   // [ch][c] tf32
    __shared__ uint32_t At[32 * AT_STR];    // [c][j] tf32

    const int t    = threadIdx.x;
    const int w    = t >> 5;
    const int lane = t & 31;
    const int gid  = lane >> 2;
    const int tg   = lane & 3;
    const int wm   = w >> 1;
    const int wn   = w & 1;

    const bool qkpath = blockIdx.y < 4;
    const int b  = blockIdx.z;
    const int o0 = (qkpath ? blockIdx.y : blockIdx.y - 4) * 128;
    const int n0 = blockIdx.x * 128;

    const float* W    = qkpath ? Wqk : Wv;
    const float* bias = qkpath ? Bqk : Bv;
    const float* Xb   = X + (size_t)b * CDIM * NPIX;

    float acc[2][8][4];
    #pragma unroll
    for (int mi = 0; mi < 2; mi++)
        #pragma unroll
        for (int nc = 0; nc < 8; nc++)
            #pragma unroll
            for (int r = 0; r < 4; r++) acc[mi][nc][r] = 0.f;

    for (int c0 = 0; c0 < CDIM; c0 += 32) {
        __syncthreads();
        #pragma unroll
        for (int r = 0; r < 16; r++) {
            int e = t + r * 256;
            int oo = e >> 5, cc = e & 31;
            Wt[oo * WT_STR + cc] = f2tf32(W[(size_t)(o0 + oo) * CDIM + c0 + cc]);
        }
        #pragma unroll
        for (int r = 0; r < 16; r++) {
            int e = t + r * 256;
            int cc = e >> 7, nn = e & 127;
            At[cc * AT_STR + nn] = f2tf32(Xb[(size_t)(c0 + cc) * NPIX + n0 + nn]);
        }
        __syncthreads();

        if (qkpath) {
            // A-frags = pixels (transposed from At), B-frags = channels (Wt)
            #pragma unroll
            for (int k8 = 0; k8 < 4; k8++) {
                const int kt = k8 * 8 + tg;
                uint32_t a0[4], a1[4];
                const int jb = wm * 32;
                a0[0] = At[kt * AT_STR + jb + gid];
                a0[1] = At[kt * AT_STR + jb + gid + 8];
                a0[2] = At[(kt + 4) * AT_STR + jb + gid];
                a0[3] = At[(kt + 4) * AT_STR + jb + gid + 8];
                a1[0] = At[kt * AT_STR + jb + 16 + gid];
                a1[1] = At[kt * AT_STR + jb + 16 + gid + 8];
                a1[2] = At[(kt + 4) * AT_STR + jb + 16 + gid];
                a1[3] = At[(kt + 4) * AT_STR + jb + 16 + gid + 8];
                #pragma unroll
                for (int nc = 0; nc < 8; nc++) {
                    const int d = wn * 64 + nc * 8 + gid;
                    uint32_t b0 = Wt[d * WT_STR + kt];
                    uint32_t b1 = Wt[d * WT_STR + kt + 4];
                    mma8(acc[0][nc], a0, b0, b1);
                    mma8(acc[1][nc], a1, b0, b1);
                }
            }
        } else {
            // A-frags = channels (Wt), B-frags = pixels (At)
            #pragma unroll
            for (int k8 = 0; k8 < 4; k8++) {
                const int kt = k8 * 8 + tg;
                uint32_t a0[4], a1[4];
                const int ob = wm * 32;
                a0[0] = Wt[(ob + gid) * WT_STR + kt];
                a0[1] = Wt[(ob + gid + 8) * WT_STR + kt];
                a0[2] = Wt[(ob + gid) * WT_STR + kt + 4];
                a0[3] = Wt[(ob + gid + 8) * WT_STR + kt + 4];
                a1[0] = Wt[(ob + 16 + gid) * WT_STR + kt];
                a1[1] = Wt[(ob + 16 + gid + 8) * WT_STR + kt];
                a1[2] = Wt[(ob + 16 + gid) * WT_STR + kt + 4];
                a1[3] = Wt[(ob + 16 + gid + 8) * WT_STR + kt + 4];
                #pragma unroll
                for (int nc = 0; nc < 8; nc++) {
                    const int n = wn * 64 + nc * 8 + gid;
                    uint32_t b0 = At[kt * AT_STR + n];
                    uint32_t b1 = At[(kt + 4) * AT_STR + n];
                    mma8(acc[0][nc], a0, b0, b1);
                    mma8(acc[1][nc], a1, b0, b1);
                }
            }
        }
    }

    if (qkpath) {
        // pack adjacent channels -> bf16 words, permuted layout
        const int head = (o0 >> 6) + wn;
        const int jb = n0 + wm * 32;
        #pragma unroll
        for (int mi = 0; mi < 2; mi++) {
            const int j_lo = jb + mi * 16 + gid;
            const int j_hi = j_lo + 8;
            #pragma unroll
            for (int half = 0; half < 2; half++) {
                uint32_t wlo[4], whi[4];
                #pragma unroll
                for (int s = 0; s < 4; s++) {
                    int nc = half * 4 + s;
                    int ch = o0 + wn * 64 + nc * 8 + 2 * tg;
                    float b0v = bias[ch], b1v = bias[ch + 1];
                    float v0 = acc[mi][nc][0] + b0v;
                    float v1 = acc[mi][nc][1] + b1v;
                    float v2 = acc[mi][nc][2] + b0v;
                    float v3 = acc[mi][nc][3] + b1v;
                    if (half == 0) { v0 *= QSCALE; v1 *= QSCALE; v2 *= QSCALE; v3 *= QSCALE; }
                    wlo[s] = pkbf(v0, v1);
                    whi[s] = pkbf(v2, v3);
                }
                uint32_t* dst = (half ? kbf : qbf) + (size_t)(b * NH + head) * NPIX * 16;
                *reinterpret_cast<uint4*>(&dst[(size_t)j_lo * 16 + 4 * tg]) =
                    make_uint4(wlo[0], wlo[1], wlo[2], wlo[3]);
                *reinterpret_cast<uint4*>(&dst[(size_t)j_hi * 16 + 4 * tg]) =
                    make_uint4(whi[0], whi[1], whi[2], whi[3]);
            }
        }
    } else {
        #pragma unroll
        for (int mi = 0; mi < 2; mi++) {
            const int o_lo = o0 + wm * 32 + mi * 16 + gid;
            const int o_hi = o_lo + 8;
            const float b_lo = bias[o_lo], b_hi = bias[o_hi];
            #pragma unroll
            for (int nc = 0; nc < 8; nc++) {
                const int n = n0 + wn * 64 + nc * 8 + 2 * tg;
                float2 lo = { acc[mi][nc][0] + b_lo, acc[mi][nc][1] + b_lo };
                float2 hi = { acc[mi][nc][2] + b_hi, acc[mi][nc][3] + b_hi };
                *reinterpret_cast<float2*>(&v4[((size_t)b * CDIM + o_lo) * NPIX + n]) = lo;
                *reinterpret_cast<float2*>(&v4[((size_t)b * CDIM + o_hi) * NPIX + n]) = hi;
            }
            uint32_t wlo[8], whi[8];
            #pragma unroll
            for (int nc = 0; nc < 8; nc++) {
                wlo[nc] = pkbf(acc[mi][nc][0] + b_lo, acc[mi][nc][1] + b_lo);
                whi[nc] = pkbf(acc[mi][nc][2] + b_hi, acc[mi][nc][3] + b_hi);
            }
            const int j2base = (n0 >> 1) + wn * 32;
            uint32_t* dlo = vbf + ((size_t)b * CDIM + o_lo) * (NPIX / 2) + j2base + 8 * tg;
            uint32_t* dhi = vbf + ((size_t)b * CDIM + o_hi) * (NPIX / 2) + j2base + 8 * tg;
            *reinterpret_cast<uint4*>(dlo)     = make_uint4(wlo[0], wlo[1], wlo[2], wlo[3]);
            *reinterpret_cast<uint4*>(dlo + 4) = make_uint4(wlo[4], wlo[5], wlo[6], wlo[7]);
            *reinterpret_cast<uint4*>(dhi)     = make_uint4(whi[0], whi[1], whi[2], whi[3]);
            *reinterpret_cast<uint4*>(dhi + 4) = make_uint4(whi[4], whi[5], whi[6], whi[7]);
        }
    }
}

// ---------------- tf32 tensor-core 1x1 conv (proj; unchanged) ----------------
__global__ __launch_bounds__(256) void conv_tc_kernel(
    const float* __restrict__ A, const float* __restrict__ A2,
    const float* __restrict__ W, const float* __restrict__ bias,
    float* __restrict__ Y, int O)
{
    __shared__ uint32_t Wt[128 * WT_STR];
    __shared__ uint32_t At[32 * AT_STR];

    const int t    = threadIdx.x;
    const int w    = t >> 5;
    const int lane = t & 31;
    const int gid  = lane >> 2;
    const int tg   = lane & 3;
    const int wm   = w >> 1;
    const int wn   = w & 1;

    const int b  = blockIdx.z;
    const int o0 = blockIdx.y * 128;
    const int n0 = blockIdx.x * 128;

    const float* Ab  = A  + (size_t)b * CDIM * NPIX;
    const float* A2b = A2 ? A2 + (size_t)b * CDIM * NPIX : nullptr;

    float acc[2][8][4];
    #pragma unroll
    for (int mi = 0; mi < 2; mi++)
        #pragma unroll
        for (int nc = 0; nc < 8; nc++)
            #pragma unroll
            for (int r = 0; r < 4; r++) acc[mi][nc][r] = 0.f;

    for (int c0 = 0; c0 < CDIM; c0 += 32) {
        __syncthreads();
        #pragma unroll
        for (int r = 0; r < 16; r++) {
            int e = t + r * 256;
            int oo = e >> 5, cc = e & 31;
            Wt[oo * WT_STR + cc] = f2tf32(W[(size_t)(o0 + oo) * CDIM + c0 + cc]);
        }
        #pragma unroll
        for (int r = 0; r < 16; r++) {
            int e = t + r * 256;
            int cc = e >> 7, nn = e & 127;
            float v = Ab[(size_t)(c0 + cc) * NPIX + n0 + nn];
            if (A2b) v += A2b[(size_t)(c0 + cc) * NPIX + n0 + nn];
            At[cc * AT_STR + nn] = f2tf32(v);
        }
        __syncthreads();

        #pragma unroll
        for (int k8 = 0; k8 < 4; k8++) {
            const int kt = k8 * 8 + tg;
            uint32_t a0[4], a1[4];
            {
                const int ob = wm * 32;
                a0[0] = Wt[(ob + gid) * WT_STR + kt];
                a0[1] = Wt[(ob + gid + 8) * WT_STR + kt];
                a0[2] = Wt[(ob + gid) * WT_STR + kt + 4];
                a0[3] = Wt[(ob + gid + 8) * WT_STR + kt + 4];
                a1[0] = Wt[(ob + 16 + gid) * WT_STR + kt];
                a1[1] = Wt[(ob + 16 + gid + 8) * WT_STR + kt];
                a1[2] = Wt[(ob + 16 + gid) * WT_STR + kt + 4];
                a1[3] = Wt[(ob + 16 + gid + 8) * WT_STR + kt + 4];
            }
            #pragma unroll
            for (int nc = 0; nc < 8; nc++) {
                const int n = wn * 64 + nc * 8 + gid;
                uint32_t b0 = At[kt * AT_STR + n];
                uint32_t b1 = At[(kt + 4) * AT_STR + n];
                mma8(acc[0][nc], a0, b0, b1);
                mma8(acc[1][nc], a1, b0, b1);
            }
        }
    }

    #pragma unroll
    for (int mi = 0; mi < 2; mi++) {
        const int o_lo = o0 + wm * 32 + mi * 16 + gid;
        const int o_hi = o_lo + 8;
        const float b_lo = bias[o_lo], b_hi = bias[o_hi];
        #pragma unroll
        for (int nc = 0; nc < 8; nc++) {
            const int n = n0 + wn * 64 + nc * 8 + 2 * tg;
            float2 lo = { acc[mi][nc][0] + b_lo, acc[mi][nc][1] + b_lo };
            float2 hi = { acc[mi][nc][2] + b_hi, acc[mi][nc][3] + b_hi };
            *reinterpret_cast<float2*>(&Y[((size_t)b * O + o_lo) * NPIX + n]) = lo;
            *reinterpret_cast<float2*>(&Y[((size_t)b * O + o_hi) * NPIX + n]) = hi;
        }
    }
}

#define KSTR 16
#define VSTR 36
#define NTILE (NPIX / 64)   // 36
#define K_BYTES (64 * KSTR * 4)   // 4096
#define V_BYTES (32 * VSTR * 4)   // 4608

// ---------------- bf16 flash attention (unchanged from R12) ----------------
__global__ __launch_bounds__(256, 4) void attn_bf16_kernel(
    const uint32_t* __restrict__ qbf, const uint32_t* __restrict__ kbf,
    const uint32_t* __restrict__ vbf, float* __restrict__ o)
{
    __shared__ __align__(16) uint32_t K2[2][64 * KSTR];
    __shared__ __align__(16) uint32_t V2[2][32 * VSTR];

    const int t    = threadIdx.x;
    const int w    = t >> 5;
    const int lane = t & 31;
    const int gid  = lane >> 2;
    const int tg   = lane & 3;

    const int bh = blockIdx.y;
    const int b  = bh >> 3, h = bh & 7;
    const int iw = blockIdx.x * 128 + w * 16;

    const uint32_t* qb = qbf + (size_t)bh * NPIX * 16;
    const uint32_t* kb = kbf + (size_t)bh * NPIX * 16;
    const uint32_t* vb = vbf + ((size_t)b * CDIM + h * HD) * (NPIX / 2);

    const uint32_t k2base = smem_u32(&K2[0][0]);
    const uint32_t v2base = smem_u32(&V2[0][0]);

    uint32_t qa[2][4];
    {
        const int ilo = iw + gid, ihi = iw + gid + 8;
        uint4 qlo = *reinterpret_cast<const uint4*>(&qb[(size_t)ilo * 16 + 4 * tg]);
        uint4 qhi = *reinterpret_cast<const uint4*>(&qb[(size_t)ihi * 16 + 4 * tg]);
        qa[0][0] = qlo.x; qa[0][2] = qlo.y; qa[1][0] = qlo.z; qa[1][2] = qlo.w;
        qa[0][1] = qhi.x; qa[0][3] = qhi.y; qa[1][1] = qhi.z; qa[1][3] = qhi.w;
    }

    float l0 = 0.f, l1 = 0.f;
    float oacc[4][4];
    #pragma unroll
    for (int i = 0; i < 4; i++)
        #pragma unroll
        for (int j = 0; j < 4; j++) oacc[i][j] = 0.f;

    const int kj = t >> 2, kc_ = t & 3;
    const int vd = t >> 3, vc_ = t & 7;
    auto load_tile = [&](int j0, int buf) {
        uint32_t kdst = k2base + buf * K_BYTES + kj * 64 + kc_ * 16;
        const uint32_t* ksrc = kb + (size_t)(j0 + kj) * 16 + kc_ * 4;
        asm volatile("cp.async.cg.shared.global [%0], [%1], 16;" :: "r"(kdst), "l"(ksrc));
        uint32_t vdst = v2base + buf * V_BYTES + vd * 144 + vc_ * 16;
        const uint32_t* vsrc = vb + (size_t)vd * (NPIX / 2) + (j0 >> 1) + vc_ * 4;
        asm volatile("cp.async.cg.shared.global [%0], [%1], 16;" :: "r"(vdst), "l"(vsrc));
        asm volatile("cp.async.commit_group;");
    };

    load_tile(0, 0);
    asm volatile("cp.async.wait_group 0;" ::: "memory");
    __syncthreads();

    for (int jt = 0; jt < NTILE; jt++) {
        const int cur = jt & 1;
        if (jt + 1 < NTILE) load_tile((jt + 1) * 64, cur ^ 1);

        uint32_t pa[4][4];
        #pragma unroll
        for (int kc = 0; kc < 4; kc++) {
            float s0[4], s1[4];
            {
                uint4 kw = *reinterpret_cast<const uint4*>(
                    &K2[cur][(16 * kc + gid) * KSTR + 4 * tg]);
                s0[0] = s0[1] = s0[2] = s0[3] = 0.f;
                mma16(s0, qa[0], kw.x, kw.y);
                mma16(s0, qa[1], kw.z, kw.w);
            }
            {
                uint4 kw = *reinterpret_cast<const uint4*>(
                    &K2[cur][(16 * kc + 8 + gid) * KSTR + 4 * tg]);
                s1[0] = s1[1] = s1[2] = s1[3] = 0.f;
                mma16(s1, qa[0], kw.x, kw.y);
                mma16(s1, qa[1], kw.z, kw.w);
            }
            s0[0] = ex2f(s0[0]); s0[1] = ex2f(s0[1]);
            s0[2] = ex2f(s0[2]); s0[3] = ex2f(s0[3]);
            s1[0] = ex2f(s1[0]); s1[1] = ex2f(s1[1]);
            s1[2] = ex2f(s1[2]); s1[3] = ex2f(s1[3]);
            l0 += s0[0] + s0[1] + s1[0] + s1[1];
            l1 += s0[2] + s0[3] + s1[2] + s1[3];
            pa[kc][0] = pkbf(s0[0], s0[1]);
            pa[kc][1] = pkbf(s0[2], s0[3]);
            pa[kc][2] = pkbf(s1[0], s1[1]);
            pa[kc][3] = pkbf(s1[2], s1[3]);
        }

        #pragma unroll
        for (int nc2 = 0; nc2 < 4; nc2++) {
            const int drow = (8 * nc2 + gid) * VSTR;
            uint4 v1 = *reinterpret_cast<const uint4*>(&V2[cur][drow + 8 * tg]);
            uint4 v2 = *reinterpret_cast<const uint4*>(&V2[cur][drow + 8 * tg + 4]);
            mma16(oacc[nc2], pa[0], v1.x, v1.y);
            mma16(oacc[nc2], pa[1], v1.z, v1.w);
            mma16(oacc[nc2], pa[2], v2.x, v2.y);
            mma16(oacc[nc2], pa[3], v2.z, v2.w);
        }

        asm volatile("cp.async.wait_group 0;" ::: "memory");
        __syncthreads();
    }

    l0 += __shfl_xor_sync(0xffffffffu, l0, 1);
    l0 += __shfl_xor_sync(0xffffffffu, l0, 2);
    l1 += __shfl_xor_sync(0xffffffffu, l1, 1);
    l1 += __shfl_xor_sync(0xffffffffu, l1, 2);

    const float inv0 = 1.f / l0, inv1 = 1.f / l1;
    float* ob = o + ((size_t)b * CDIM + h * HD) * NPIX;
    const int i_lo = iw + gid, i_hi = iw + gid + 8;
    #pragma unroll
    for (int nc2 = 0; nc2 < 4; nc2++) {
        int d = 8 * nc2 + 2 * tg;
        ob[(size_t)d * NPIX + i_lo]       = oacc[nc2][0] * inv0;
        ob[(size_t)(d + 1) * NPIX + i_lo] = oacc[nc2][1] * inv0;
        ob[(size_t)d * NPIX + i_hi]       = oacc[nc2][2] * inv1;
        ob[(size_t)(d + 1) * NPIX + i_hi] = oacc[nc2][3] * inv1;
    }
}

// ---------------- depthwise 3x3 ----------------
__global__ __launch_bounds__(256) void dwconv_kernel(
    const float* __restrict__ v4, const float* __restrict__ w_pe,
    const float* __restrict__ b_pe, float* __restrict__ pe)
{
    __shared__ float plane[NPIX];
    const int bc = blockIdx.x;
    const int c  = bc & (CDIM - 1);
    const int t  = threadIdx.x;

    const float* src = v4 + (size_t)bc * NPIX;
    #pragma unroll
    for (int r = 0; r < 9; r++) plane[t + r * 256] = src[t + r * 256];

    float w[9];
    #pragma unroll
    for (int k = 0; k < 9; k++) w[k] = w_pe[c * 9 + k];
    const float bias = b_pe[c];
    __syncthreads();

    float* dst = pe + (size_t)bc * NPIX;
    #pragma unroll
    for (int r = 0; r < 9; r++) {
        int idx = t + r * 256;
        int y = idx / HPW, x = idx - y * HPW;
        float s = bias;
        #pragma unroll
        for (int dy = 0; dy < 3; dy++) {
            int yy = y + dy - 1;
            if (yy < 0 || yy >= HPW) continue;
            #pragma unroll
            for (int dx = 0; dx < 3; dx++) {
                int xx = x + dx - 1;
                if (xx < 0 || xx >= HPW) continue;
                s += plane[yy * HPW + xx] * w[dy * 3 + dx];
            }
        }
        dst[idx] = s;
    }
}

// ---------------- launch (single stream, fused producers) ----------------
extern "C" void kernel_launch(void* const* d_in, const int* in_sizes, int n_in,
                              void* d_out, int out_size)
{
    const float* x      = (const float*)d_in[0];
    const float* w_qk   = (const float*)d_in[1];
    const float* b_qk   = (const float*)d_in[2];
    const float* w_v    = (const float*)d_in[3];
    const float* b_v    = (const float*)d_in[4];
    const float* w_pe   = (const float*)d_in[5];
    const float* b_pe   = (const float*)d_in[6];
    const float* w_proj = (const float*)d_in[7];
    const float* b_proj = (const float*)d_in[8];
    float* out = (float*)d_out;

    float *v4p, *pep, *op;
    uint32_t *qbfp, *kbfp, *vbfp;
    cudaGetSymbolAddress((void**)&v4p, g_v4);
    cudaGetSymbolAddress((void**)&pep, g_pe);
    cudaGetSymbolAddress((void**)&op,  g_o);
    cudaGetSymbolAddress((void**)&qbfp, g_qbf);
    cudaGetSymbolAddress((void**)&kbfp, g_kbf);
    cudaGetSymbolAddress((void**)&vbfp, g_vbf);

    // fused qk + v producer GEMMs (432 CTAs, one wave-set)
    producer_tc_kernel<<<dim3(NPIX/128, 6, BSZ), 256>>>(
        x, w_qk, b_qk, w_v, b_v, qbfp, kbfp, v4p, vbfp);
    dwconv_kernel<<<BSZ * CDIM, 256>>>(v4p, w_pe, b_pe, pep);
    attn_bf16_kernel<<<dim3(NPIX/128, BSZ * NH), 256>>>(qbfp, kbfp, vbfp, op);
    conv_tc_kernel<<<dim3(NPIX/128, CDIM/128, BSZ), 256>>>(op, pep, w_proj, b_proj, out, CDIM);
}